// round 1
// baseline (speedup 1.0000x reference)
#include <cuda_runtime.h>

#define NA 96
#define NB 96
#define NS 64
#define KS 15
#define RAD 7
#define NTHREADS 256

__global__ __launch_bounds__(NTHREADS)
void latent_lookup_kernel(const float* __restrict__ q,
                          const float* __restrict__ rel,
                          const float* __restrict__ origin,
                          const float* __restrict__ spacing,
                          const float* __restrict__ temp,
                          float* __restrict__ out, int batch) {
    const int b = blockIdx.x;
    const int tid = threadIdx.x;

    __shared__ float sh_q[3];
    __shared__ float ex[KS], ey[KS], ez[KS];
    __shared__ int   xoff[KS];
    __shared__ float s_axis[3];
    __shared__ float red[NTHREADS / 32];
    __shared__ int   vox[3];
    __shared__ float sh_invt;

    if (tid < 3) sh_q[tid] = q[b * 3 + tid];
    if (tid == 0) sh_invt = 1.0f / (temp[0] + 1e-8f);
    __syncthreads();

    const float q0 = sh_q[0], q1 = sh_q[1], q2 = sh_q[2];
    const float inv_t = sh_invt;

    // ---- voxel = clip(round((q-origin)/spacing), 1, N-2) per axis ----
    if (tid < 3) {
        float rp = (sh_q[tid] - origin[tid]) / spacing[tid];
        int n = (tid == 0) ? NA : ((tid == 1) ? NB : NS);
        int v = (int)rintf(rp);          // round-half-even, matches jnp.round
        v = min(max(v, 1), n - 2);
        vox[tid] = v;
    }
    __syncthreads();

    // ---- per-axis separable softmax weight tables (45 exps total) ----
    if (tid < 3 * KS) {
        int axis = tid / KS;
        int o = tid % KS;
        int n = (axis == 0) ? NA : ((axis == 1) ? NB : NS);
        int c = vox[axis] + o - RAD;
        c = min(max(c, 0), n - 1);
        float d = sh_q[axis] - (float)c;
        float e = __expf(-d * d * inv_t);
        if (axis == 0) { ex[o] = e; xoff[o] = c * (NB * NS); }
        else if (axis == 1) { ey[o] = e; }
        else { ez[o] = e; }
    }
    __syncthreads();

    // ---- per-axis sums -> factorized softmax denominator ----
    if (tid < 3) {
        const float* a = (tid == 0) ? ex : ((tid == 1) ? ey : ez);
        float s = 0.0f;
        #pragma unroll
        for (int i = 0; i < KS; i++) s += a[i];
        s_axis[tid] = s;
    }

    // ---- hard path: 8 corner candidates, replicate reference fp32 math ----
    if (tid == 32) {  // warp 1, runs concurrently with warp-0 axis sums
        float qn = __fadd_rn(__fadd_rn(__fmul_rn(q0, q0), __fmul_rn(q1, q1)),
                             __fmul_rn(q2, q2));
        int f0 = (int)floorf(q0);
        int f1 = (int)floorf(q1);
        int f2 = (int)floorf(q2);
        float best = 3.4e38f;
        int bestIdx = 0x7fffffff;
        #pragma unroll
        for (int ii = 0; ii < 2; ii++) {
            #pragma unroll
            for (int jj = 0; jj < 2; jj++) {
                #pragma unroll
                for (int kk = 0; kk < 2; kk++) {
                    int a = min(max(f0 + ii, 0), NA - 1);
                    int c1 = min(max(f1 + jj, 0), NB - 1);
                    int c2 = min(max(f2 + kk, 0), NS - 1);
                    float in_ = (float)(a * a + c1 * c1 + c2 * c2);  // exact ints
                    float dot = __fmaf_rn(q2, (float)c2,
                                 __fmaf_rn(q1, (float)c1,
                                  __fmul_rn(q0, (float)a)));
                    float d = __fsub_rn(__fadd_rn(qn, in_), __fmul_rn(2.0f, dot));
                    int flat = (a * NB + c1) * NS + c2;
                    if (d < best || (d == best && flat < bestIdx)) {
                        best = d;
                        bestIdx = flat;
                    }
                }
            }
        }
        out[b] = rel[bestIdx];
    }
    __syncthreads();

    // ---- soft numerator: 225 threads x 15 x-planes, LDG+FMA inner loop ----
    float vpart = 0.0f;
    if (tid < KS * KS) {
        int dj = tid / KS;
        int dk = tid % KS;
        int y = min(max(vox[1] + dj - RAD, 0), NB - 1);
        int z = min(max(vox[2] + dk - RAD, 0), NS - 1);
        int base = y * NS + z;
        float acc = 0.0f;
        #pragma unroll
        for (int di = 0; di < KS; di++) {
            acc = __fmaf_rn(ex[di], __ldg(&rel[xoff[di] + base]), acc);
        }
        vpart = ey[dj] * ez[dk] * acc;
    }

    // ---- block reduction of numerator ----
    #pragma unroll
    for (int o = 16; o > 0; o >>= 1)
        vpart += __shfl_down_sync(0xffffffff, vpart, o);
    if ((tid & 31) == 0) red[tid >> 5] = vpart;
    __syncthreads();
    if (tid == 0) {
        float num = 0.0f;
        #pragma unroll
        for (int w = 0; w < NTHREADS / 32; w++) num += red[w];
        float den = s_axis[0] * s_axis[1] * s_axis[2];
        out[batch + b] = num / den;
    }
}

extern "C" void kernel_launch(void* const* d_in, const int* in_sizes, int n_in,
                              void* d_out, int out_size) {
    // metadata order: query_vectors, indices_3d, relevant_metrics_3d,
    //                 grid_origin, grid_spacing, temperature, kernel_size
    const float* q       = (const float*)d_in[0];
    const float* rel     = (const float*)d_in[2];
    const float* origin  = (const float*)d_in[3];
    const float* spacing = (const float*)d_in[4];
    const float* temp    = (const float*)d_in[5];
    float* out = (float*)d_out;
    int batch = in_sizes[0] / 3;

    latent_lookup_kernel<<<batch, NTHREADS>>>(q, rel, origin, spacing, temp,
                                              out, batch);
}

// round 2
// speedup vs baseline: 1.3527x; 1.3527x over previous
#include <cuda_runtime.h>

#define NA 96
#define NB 96
#define NS 64
#define KS 15
#define RAD 7
#define NTHREADS 256

__global__ __launch_bounds__(NTHREADS)
void latent_lookup_kernel(const float* __restrict__ q,
                          const float* __restrict__ rel,
                          const float* __restrict__ origin,
                          const float* __restrict__ spacing,
                          const float* __restrict__ temp,
                          float* __restrict__ out, int batch) {
    const int b = blockIdx.x;
    const int tid = threadIdx.x;

    __shared__ float ex[KS];
    __shared__ float red_num[NTHREADS / 32];
    __shared__ float red_den[NTHREADS / 32];
    __shared__ float s_sx;

    // ---- every thread loads q + params (broadcast loads, L1-coalesced) ----
    const float q0 = __ldg(&q[b * 3 + 0]);
    const float q1 = __ldg(&q[b * 3 + 1]);
    const float q2 = __ldg(&q[b * 3 + 2]);
    const float o0 = __ldg(&origin[0]), o1 = __ldg(&origin[1]), o2 = __ldg(&origin[2]);
    const float s0 = __ldg(&spacing[0]), s1 = __ldg(&spacing[1]), s2 = __ldg(&spacing[2]);
    const float inv_t = 1.0f / (__ldg(&temp[0]) + 1e-8f);

    // ---- per-thread voxel (no shared round-trip) ----
    const int v0 = min(max((int)rintf((q0 - o0) / s0), 1), NA - 2);
    const int v1 = min(max((int)rintf((q1 - o1) / s1), 1), NB - 2);
    const int v2 = min(max((int)rintf((q2 - o2) / s2), 1), NS - 2);

    // ---- issue all 15 x-plane loads FIRST (addresses need only vox) ----
    const int dj = tid / KS;            // valid for tid < 225
    const int dk = tid - dj * KS;
    const int y = min(max(v1 + dj - RAD, 0), NB - 1);
    const int z = min(max(v2 + dk - RAD, 0), NS - 1);
    const int base = y * NS + z;

    float m[KS];
    if (tid < KS * KS) {
        #pragma unroll
        for (int di = 0; di < KS; di++) {
            int cx = min(max(v0 + di - RAD, 0), NA - 1);
            m[di] = __ldg(&rel[cx * (NB * NS) + base]);
        }
    }

    // ---- overlap: exp tables while loads are in flight ----
    if (tid < KS) {
        int c = min(max(v0 + tid - RAD, 0), NA - 1);
        float d = q0 - (float)c;
        ex[tid] = __expf(-d * d * inv_t);
    }

    float eyez = 0.0f;
    if (tid < KS * KS) {
        float dy = q1 - (float)y;
        float dz = q2 - (float)z;
        eyez = __expf(-(dy * dy + dz * dz) * inv_t);
    }

    // ---- hard path on idle lane 255 (concurrent with everything) ----
    if (tid == 255) {
        float qn = __fadd_rn(__fadd_rn(__fmul_rn(q0, q0), __fmul_rn(q1, q1)),
                             __fmul_rn(q2, q2));
        int f0 = (int)floorf(q0);
        int f1 = (int)floorf(q1);
        int f2 = (int)floorf(q2);
        float best = 3.4e38f;
        int bestIdx = 0x7fffffff;
        #pragma unroll
        for (int ii = 0; ii < 2; ii++)
            #pragma unroll
            for (int jj = 0; jj < 2; jj++)
                #pragma unroll
                for (int kk = 0; kk < 2; kk++) {
                    int a  = min(max(f0 + ii, 0), NA - 1);
                    int c1 = min(max(f1 + jj, 0), NB - 1);
                    int c2 = min(max(f2 + kk, 0), NS - 1);
                    float in_ = (float)(a * a + c1 * c1 + c2 * c2);
                    float dot = __fmaf_rn(q2, (float)c2,
                                 __fmaf_rn(q1, (float)c1,
                                  __fmul_rn(q0, (float)a)));
                    float d = __fsub_rn(__fadd_rn(qn, in_), __fmul_rn(2.0f, dot));
                    int flat = (a * NB + c1) * NS + c2;
                    if (d < best || (d == best && flat < bestIdx)) {
                        best = d; bestIdx = flat;
                    }
                }
        out[b] = __ldg(&rel[bestIdx]);
    }

    __syncthreads();   // ex[] table visible

    // ---- spare thread computes sum(ex) in parallel with the FMA loop ----
    if (tid == 240) {
        float sx = 0.0f;
        #pragma unroll
        for (int i = 0; i < KS; i++) sx += ex[i];
        s_sx = sx;
    }

    // ---- numerator: dot(ex, m) per column; fold ey*ez factor ----
    float num = 0.0f;
    if (tid < KS * KS) {
        float acc = 0.0f;
        #pragma unroll
        for (int di = 0; di < KS; di++)
            acc = __fmaf_rn(ex[di], m[di], acc);
        num = eyez * acc;
    }

    // ---- pair reduction: (numerator, sum of ey*ez) ----
    #pragma unroll
    for (int o = 16; o > 0; o >>= 1) {
        num  += __shfl_down_sync(0xffffffff, num, o);
        eyez += __shfl_down_sync(0xffffffff, eyez, o);
    }
    if ((tid & 31) == 0) {
        red_num[tid >> 5] = num;
        red_den[tid >> 5] = eyez;
    }
    __syncthreads();
    if (tid == 0) {
        float n = 0.0f, dsum = 0.0f;
        #pragma unroll
        for (int w = 0; w < NTHREADS / 32; w++) {
            n += red_num[w];
            dsum += red_den[w];
        }
        out[batch + b] = n / (s_sx * dsum);
    }
}

extern "C" void kernel_launch(void* const* d_in, const int* in_sizes, int n_in,
                              void* d_out, int out_size) {
    const float* q       = (const float*)d_in[0];
    const float* rel     = (const float*)d_in[2];
    const float* origin  = (const float*)d_in[3];
    const float* spacing = (const float*)d_in[4];
    const float* temp    = (const float*)d_in[5];
    float* out = (float*)d_out;
    int batch = in_sizes[0] / 3;

    latent_lookup_kernel<<<batch, NTHREADS>>>(q, rel, origin, spacing, temp,
                                              out, batch);
}